// round 1
// baseline (speedup 1.0000x reference)
#include <cuda_runtime.h>

// Problem: N=M=16384 points, D=16, Poincare-ball averaged Hausdorff loss.
// Pipeline:
//   1) pre_kernel: per-point squared norms, 1/(1-n2), init min arrays to +inf
//   2) pair_kernel: 128x128 tiles, per-thread 8x8 register tile, d-packed
//      fma.rn.f32x2 dot products; row-min of sqdist*invy, col-min of sqdist*invx;
//      block-reduce + global atomicMin (float-as-int, values >= 0)
//   3) finalize_kernel: arcosh(1 + 2*m*inv) per row/col, 128 block partials
//   4) final_sum: sum partials -> d_out[0]

#define NMAX 16384

__device__ float g_xn[NMAX], g_invx[NMAX], g_yn[NMAX], g_invy[NMAX];
__device__ int   g_rowmin[NMAX], g_colmin[NMAX];
__device__ float g_part[128];

// packed fp32x2 FMA (Blackwell, PTX-only)
#define FMA2(c, a, b) \
    asm("fma.rn.f32x2 %0, %1, %2, %3;" : "=l"(c) : "l"(a), "l"(b), "l"(c))

__global__ void pre_kernel(const float* __restrict__ X,
                           const float* __restrict__ Y, int N, int M) {
    int idx = blockIdx.x * 256 + threadIdx.x;
    if (idx < N) {
        const float4* p = (const float4*)(X + (size_t)idx * 16);
        float4 a = p[0], b = p[1], c = p[2], d = p[3];
        float s = a.x*a.x + a.y*a.y + a.z*a.z + a.w*a.w
                + b.x*b.x + b.y*b.y + b.z*b.z + b.w*b.w
                + c.x*c.x + c.y*c.y + c.z*c.z + c.w*c.w
                + d.x*d.x + d.y*d.y + d.z*d.z + d.w*d.w;
        g_xn[idx]     = s;
        g_invx[idx]   = 1.0f / (1.0f - s);
        g_rowmin[idx] = 0x7f800000;  // +inf bits
    }
    if (idx < M) {
        const float4* p = (const float4*)(Y + (size_t)idx * 16);
        float4 a = p[0], b = p[1], c = p[2], d = p[3];
        float s = a.x*a.x + a.y*a.y + a.z*a.z + a.w*a.w
                + b.x*b.x + b.y*b.y + b.z*b.z + b.w*b.w
                + c.x*c.x + c.y*c.y + c.z*c.z + c.w*c.w
                + d.x*d.x + d.y*d.y + d.z*d.z + d.w*d.w;
        g_yn[idx]     = s;
        g_invy[idx]   = 1.0f / (1.0f - s);
        g_colmin[idx] = 0x7f800000;
    }
}

// 128x128 tile per block; 256 threads (tx 0..15, ty 0..15); 8x8 pairs/thread.
// d dimension (16) packed as 8 f32x2 lanes-pairs.
__global__ __launch_bounds__(256, 1)
void pair_kernel(const float* __restrict__ X, const float* __restrict__ Y,
                 int N, int M) {
    __shared__ __align__(16) unsigned long long Xp[8][128];  // [d-pair][row]
    __shared__ __align__(16) unsigned long long Yp[8][128];
    __shared__ float xns[128], invxs[128], yns[128], invys[128];
    __shared__ float colred[16 * 128];

    const int tid = threadIdx.x;
    const int tx  = tid & 15;
    const int ty  = tid >> 4;
    const int i0  = blockIdx.y * 128;
    const int j0  = blockIdx.x * 128;

    // ---- load tiles: each thread loads 8 floats (half a point) of X and Y
    {
        int r = tid >> 1, h = tid & 1;
        const ulonglong2* xg =
            (const ulonglong2*)(X + (size_t)(i0 + r) * 16 + h * 8);
        ulonglong2 v0 = xg[0], v1 = xg[1];
        Xp[h * 4 + 0][r] = v0.x;
        Xp[h * 4 + 1][r] = v0.y;
        Xp[h * 4 + 2][r] = v1.x;
        Xp[h * 4 + 3][r] = v1.y;
        const ulonglong2* yg =
            (const ulonglong2*)(Y + (size_t)(j0 + r) * 16 + h * 8);
        ulonglong2 w0 = yg[0], w1 = yg[1];
        Yp[h * 4 + 0][r] = w0.x;
        Yp[h * 4 + 1][r] = w0.y;
        Yp[h * 4 + 2][r] = w1.x;
        Yp[h * 4 + 3][r] = w1.y;
    }
    if (tid < 128) {
        xns[tid]   = g_xn[i0 + tid];
        invxs[tid] = g_invx[i0 + tid];
        yns[tid]   = g_yn[j0 + tid];
        invys[tid] = g_invy[j0 + tid];
    }
    __syncthreads();

    // ---- mainloop: acc[a][b] accumulates (dot_even, dot_odd) over d-pairs
    unsigned long long acc[8][8];
#pragma unroll
    for (int a = 0; a < 8; a++)
#pragma unroll
        for (int b = 0; b < 8; b++) acc[a][b] = 0ULL;

#pragma unroll
    for (int dd = 0; dd < 8; dd++) {
        unsigned long long xp[8], yp[8];
#pragma unroll
        for (int q = 0; q < 4; q++) {
            ulonglong2 xv = *(const ulonglong2*)&Xp[dd][q * 32 + 2 * ty];
            xp[2 * q]     = xv.x;
            xp[2 * q + 1] = xv.y;
            ulonglong2 yv = *(const ulonglong2*)&Yp[dd][q * 32 + 2 * tx];
            yp[2 * q]     = yv.x;
            yp[2 * q + 1] = yv.y;
        }
#pragma unroll
        for (int a = 0; a < 8; a++)
#pragma unroll
            for (int b = 0; b < 8; b++) FMA2(acc[a][b], xp[a], yp[b]);
    }

    // ---- epilogue: sqdist = xn + yn - 2*dot; track scaled mins
    float xnA[8], ixA[8], ynB[8], iyB[8];
#pragma unroll
    for (int a = 0; a < 8; a++) {
        int il = ((a >> 1) << 5) + 2 * ty + (a & 1);
        xnA[a] = xns[il];
        ixA[a] = invxs[il];
    }
#pragma unroll
    for (int b = 0; b < 8; b++) {
        int jl = ((b >> 1) << 5) + 2 * tx + (b & 1);
        ynB[b] = yns[jl];
        iyB[b] = invys[jl];
    }

    float tmin[8], smin[8];
#pragma unroll
    for (int k = 0; k < 8; k++) {
        tmin[k] = __int_as_float(0x7f800000);
        smin[k] = __int_as_float(0x7f800000);
    }

#pragma unroll
    for (int a = 0; a < 8; a++) {
#pragma unroll
        for (int b = 0; b < 8; b++) {
            union { unsigned long long u; float2 f; } cvt;
            cvt.u     = acc[a][b];
            float dot = cvt.f.x + cvt.f.y;
            float sq  = fmaf(-2.0f, dot, xnA[a] + ynB[b]);
            tmin[a]   = fminf(tmin[a], sq * iyB[b]);
            smin[b]   = fminf(smin[b], sq * ixA[a]);
        }
    }

    // ---- row mins: reduce across tx (lanes 0..15 / 16..31 of the warp)
#pragma unroll
    for (int a = 0; a < 8; a++) {
        float v = fmaxf(tmin[a], 0.0f);
#pragma unroll
        for (int off = 1; off < 16; off <<= 1)
            v = fminf(v, __shfl_xor_sync(0xffffffffu, v, off));
        if (tx == 0) {
            int il = ((a >> 1) << 5) + 2 * ty + (a & 1);
            atomicMin(&g_rowmin[i0 + il], __float_as_int(v));
        }
    }

    // ---- col mins: stage per-ty rows in smem, reduce across ty
#pragma unroll
    for (int b = 0; b < 8; b++) {
        int jl = ((b >> 1) << 5) + 2 * tx + (b & 1);
        colred[ty * 128 + jl] = fmaxf(smin[b], 0.0f);
    }
    __syncthreads();
    if (tid < 128) {
        float v = colred[tid];
#pragma unroll
        for (int k = 1; k < 16; k++) v = fminf(v, colred[k * 128 + tid]);
        atomicMin(&g_colmin[j0 + tid], __float_as_int(v));
    }
}

// blocks 0..63 -> rows, 64..127 -> cols; each block covers 256 entries exactly.
__global__ void finalize_kernel(int N, int M) {
    __shared__ float red[256];
    int  b     = blockIdx.x;
    bool isRow = (b < 64);
    int  idx   = (isRow ? b : b - 64) * 256 + threadIdx.x;
    float val  = 0.0f;
    int   lim  = isRow ? N : M;
    if (idx < lim) {
        float m   = fmaxf(__int_as_float(isRow ? g_rowmin[idx] : g_colmin[idx]),
                          0.0f);
        float inv = isRow ? g_invx[idx] : g_invy[idx];
        float u   = fmaf(2.0f * m, inv, 1.0f);
        val       = logf(u + sqrtf(fmaxf(u * u - 1.0f, 0.0f)));
    }
    red[threadIdx.x] = val;
    __syncthreads();
    for (int s = 128; s > 0; s >>= 1) {
        if (threadIdx.x < s) red[threadIdx.x] += red[threadIdx.x + s];
        __syncthreads();
    }
    if (threadIdx.x == 0)
        g_part[b] = red[0] * (isRow ? 1.0f / (float)N : 1.0f / (float)M);
}

__global__ void final_sum(float* out) {
    __shared__ float red[128];
    red[threadIdx.x] = g_part[threadIdx.x];
    __syncthreads();
    for (int s = 64; s > 0; s >>= 1) {
        if (threadIdx.x < s) red[threadIdx.x] += red[threadIdx.x + s];
        __syncthreads();
    }
    if (threadIdx.x == 0) out[0] = red[0];
}

extern "C" void kernel_launch(void* const* d_in, const int* in_sizes, int n_in,
                              void* d_out, int out_size) {
    const float* X = (const float*)d_in[0];  // set1: [N,16]
    const float* Y = (const float*)d_in[1];  // set2: [M,16]
    int N = in_sizes[0] / 16;
    int M = in_sizes[1] / 16;

    int mx = (N > M ? N : M);
    pre_kernel<<<(mx + 255) / 256, 256>>>(X, Y, N, M);

    dim3 grid(M / 128, N / 128);
    pair_kernel<<<grid, 256>>>(X, Y, N, M);

    finalize_kernel<<<128, 256>>>(N, M);
    final_sum<<<1, 128>>>((float*)d_out);
}

// round 3
// speedup vs baseline: 2.0302x; 2.0302x over previous
#include <cuda_runtime.h>
#include <cuda_bf16.h>
#include <cstdint>

// ============================================================================
// Hyperbolic averaged Hausdorff loss via legacy tensor-core mma.sync (bf16).
//
// dot(X_i,Y_j) with fp32-ish accuracy using a bf16 hi/lo split, K widened to
// fold the norm terms directly into the accumulator:
//   A_i cols: [xh(16) | xl(16) | xh(16) | xn_h, xn_l, 1, 1 | 0 x12]   (K=64)
//   B_j cols: [yh(16) | yh(16) | yl(16) | -.5, -.5, m_h, m_l | 0 x12]
//   where m = -yn/2.  =>  acc_ij = dot_ij - (xn_i + yn_j)/2
//   sqdist = -2*acc ; row-min of sqdist*invy = min_j acc*( -2*invy_j )
//            col-min of sqdist*invx = min_i acc*( -2*invx_i )
// arcosh is monotone so mins commute; finalize applies arcosh to the mins.
// ============================================================================

#define NPTS 16384

__device__ float g_invx[NPTS], g_invy[NPTS];
__device__ int   g_rowmin[NPTS], g_colmin[NPTS];
__device__ float g_part[128];
__device__ __nv_bfloat16 g_A[NPTS * 64];
__device__ __nv_bfloat16 g_B[NPTS * 64];

__device__ __forceinline__ uint32_t smem_u32(const void* p) {
    uint32_t a;
    asm("{ .reg .u64 t; cvta.to.shared.u64 t, %1; cvt.u32.u64 %0, t; }"
        : "=r"(a) : "l"(p));
    return a;
}
#define SMEM_SWZ(o) ((o) ^ ((((o) >> 3) & 0x70)))

#define LDSM4(r, addr)                                                      \
    asm volatile("ldmatrix.sync.aligned.m8n8.x4.shared.b16 "                \
                 "{%0,%1,%2,%3}, [%4];"                                     \
                 : "=r"((r)[0]), "=r"((r)[1]), "=r"((r)[2]), "=r"((r)[3])   \
                 : "r"(addr))

#define MMA16816(d, a, b0, b1)                                              \
    asm volatile("mma.sync.aligned.m16n8k16.row.col.f32.bf16.bf16.f32 "     \
                 "{%0,%1,%2,%3}, {%4,%5,%6,%7}, {%8,%9}, {%0,%1,%2,%3};"    \
                 : "+f"((d)[0]), "+f"((d)[1]), "+f"((d)[2]), "+f"((d)[3])   \
                 : "r"((a)[0]), "r"((a)[1]), "r"((a)[2]), "r"((a)[3]),      \
                   "r"(b0), "r"(b1))

// ---------------------------------------------------------------- prep kernel
union BU { __nv_bfloat16 b; unsigned short u; };

__device__ __forceinline__ unsigned short bfu(float x) {
    BU t; t.b = __float2bfloat16(x); return t.u;
}
__device__ __forceinline__ float bff(unsigned short u) {
    BU t; t.u = u; return __bfloat162float(t.b);
}

__device__ __forceinline__ void split_store(const float* src, int idx,
                                            __nv_bfloat16* dst, bool isA,
                                            float* inv, int* mn) {
    float v[16];
    const float4* p = (const float4*)(src + (size_t)idx * 16);
    float4 q0 = p[0], q1 = p[1], q2 = p[2], q3 = p[3];
    v[0]=q0.x; v[1]=q0.y; v[2]=q0.z; v[3]=q0.w;
    v[4]=q1.x; v[5]=q1.y; v[6]=q1.z; v[7]=q1.w;
    v[8]=q2.x; v[9]=q2.y; v[10]=q2.z; v[11]=q2.w;
    v[12]=q3.x; v[13]=q3.y; v[14]=q3.z; v[15]=q3.w;
    float s = 0.f;
#pragma unroll
    for (int d = 0; d < 16; d++) s += v[d] * v[d];
    inv[idx] = 1.0f / (1.0f - s);
    mn[idx]  = 0x7f800000;

    unsigned short hi[16], lo[16];
#pragma unroll
    for (int d = 0; d < 16; d++) {
        hi[d] = bfu(v[d]);
        lo[d] = bfu(v[d] - bff(hi[d]));
    }
    uint32_t w[32];
#pragma unroll
    for (int k = 0; k < 8; k++) {
        uint32_t hp = (uint32_t)hi[2*k] | ((uint32_t)hi[2*k+1] << 16);
        uint32_t lp = (uint32_t)lo[2*k] | ((uint32_t)lo[2*k+1] << 16);
        w[k]      = hp;
        w[8 + k]  = isA ? lp : hp;
        w[16 + k] = isA ? hp : lp;
    }
    if (isA) {
        unsigned short nh = bfu(s);
        unsigned short nl = bfu(s - bff(nh));
        unsigned short one = bfu(1.0f);
        w[24] = (uint32_t)nh | ((uint32_t)nl << 16);
        w[25] = (uint32_t)one | ((uint32_t)one << 16);
    } else {
        float m = -0.5f * s;
        unsigned short mh = bfu(m);
        unsigned short ml = bfu(m - bff(mh));
        unsigned short nhalf = bfu(-0.5f);
        w[24] = (uint32_t)nhalf | ((uint32_t)nhalf << 16);
        w[25] = (uint32_t)mh | ((uint32_t)ml << 16);
    }
#pragma unroll
    for (int k = 26; k < 32; k++) w[k] = 0u;

    uint4* d4 = (uint4*)(dst + (size_t)idx * 64);
#pragma unroll
    for (int c = 0; c < 8; c++)
        d4[c] = make_uint4(w[4*c], w[4*c+1], w[4*c+2], w[4*c+3]);
}

__global__ void prep_kernel(const float* __restrict__ X,
                            const float* __restrict__ Y, int N, int M) {
    int idx = blockIdx.x * 256 + threadIdx.x;
    if (idx < N) split_store(X, idx, g_A, true,  g_invx, g_rowmin);
    if (idx < M) split_store(Y, idx, g_B, false, g_invy, g_colmin);
}

// ---------------------------------------------------------------- pair kernel
__global__ void __launch_bounds__(256, 2) pair_mma_kernel() {
    __shared__ __align__(16) char sA[128 * 128];   // 128 rows x 128B (K=64 bf16)
    __shared__ __align__(16) char sB[128 * 128];
    __shared__ float s_nx[128], s_ny[128];
    __shared__ float rowpart[2][128];
    __shared__ float colpart[4][128];

    const int tid  = threadIdx.x;
    const int wid  = tid >> 5;
    const int lane = tid & 31;
    const int i0   = blockIdx.y * 128;
    const int j0   = blockIdx.x * 128;

    // ---- load tiles (SW128 swizzled)
    {
        const uint4* Ag = (const uint4*)g_A + (size_t)i0 * 8;
        const uint4* Bg = (const uint4*)g_B + (size_t)j0 * 8;
#pragma unroll
        for (int k = tid; k < 1024; k += 256) {
            int r = k >> 3, c = k & 7;
            *(uint4*)(sA + SMEM_SWZ(r * 128 + c * 16)) = Ag[k];
            *(uint4*)(sB + SMEM_SWZ(r * 128 + c * 16)) = Bg[k];
        }
    }
    if (tid < 128) {
        s_nx[tid] = -2.0f * g_invx[i0 + tid];
        s_ny[tid] = -2.0f * g_invy[j0 + tid];
    }
    __syncthreads();

    const uint32_t sAb = smem_u32(sA);
    const uint32_t sBb = smem_u32(sB);
    const int wr = wid & 3;          // warp row: 32 i-rows
    const int wc = wid >> 2;         // warp col: 64 j-cols
    const int lr = lane & 15;
    const int lc = lane >> 4;
    const float INF = __int_as_float(0x7f800000);

    float nxv[4];
#pragma unroll
    for (int mt = 0; mt < 2; mt++)
#pragma unroll
        for (int rr = 0; rr < 2; rr++)
            nxv[2*mt+rr] = s_nx[32*wr + 16*mt + 8*rr + (lane >> 2)];

    float rmin[4] = {INF, INF, INF, INF};

#pragma unroll
    for (int h = 0; h < 2; h++) {   // 32-col halves of the warp's 64 cols
        float nyv[8];
#pragma unroll
        for (int nt = 0; nt < 4; nt++)
#pragma unroll
            for (int c = 0; c < 2; c++)
                nyv[2*nt+c] = s_ny[64*wc + 32*h + 8*nt + 2*(lane & 3) + c];

        float acc[2][4][4];
#pragma unroll
        for (int mt = 0; mt < 2; mt++)
#pragma unroll
            for (int nt = 0; nt < 4; nt++)
#pragma unroll
                for (int e = 0; e < 4; e++) acc[mt][nt][e] = 0.0f;

#pragma unroll
        for (int ks = 0; ks < 4; ks++) {
            uint32_t a[2][4], b[2][4];
#pragma unroll
            for (int mt = 0; mt < 2; mt++) {
                int row = 32*wr + 16*mt + lr;
                LDSM4(a[mt], sAb + SMEM_SWZ(row*128 + ks*32 + lc*16));
            }
#pragma unroll
            for (int np = 0; np < 2; np++) {
                int row = 64*wc + 32*h + 16*np + lr;
                LDSM4(b[np], sBb + SMEM_SWZ(row*128 + ks*32 + lc*16));
            }
#pragma unroll
            for (int mt = 0; mt < 2; mt++)
#pragma unroll
                for (int nt = 0; nt < 4; nt++) {
                    int np = nt >> 1, od = nt & 1;
                    MMA16816(acc[mt][nt], a[mt], b[np][od], b[np][od+2]);
                }
        }

        // ---- epilogue: 2 MUL + 2 MIN per pair
        float cmin[8];
#pragma unroll
        for (int k = 0; k < 8; k++) cmin[k] = INF;
#pragma unroll
        for (int mt = 0; mt < 2; mt++)
#pragma unroll
            for (int nt = 0; nt < 4; nt++) {
                float* c = acc[mt][nt];
                rmin[2*mt]   = fminf(rmin[2*mt],
                               fminf(c[0]*nyv[2*nt], c[1]*nyv[2*nt+1]));
                rmin[2*mt+1] = fminf(rmin[2*mt+1],
                               fminf(c[2]*nyv[2*nt], c[3]*nyv[2*nt+1]));
                cmin[2*nt]   = fminf(cmin[2*nt],
                               fminf(c[0]*nxv[2*mt], c[2]*nxv[2*mt+1]));
                cmin[2*nt+1] = fminf(cmin[2*nt+1],
                               fminf(c[1]*nxv[2*mt], c[3]*nxv[2*mt+1]));
            }

        // reduce col-mins across lanes sharing (lane&3): xor 4, 8, 16
#pragma unroll
        for (int k = 0; k < 8; k++) {
            float v = cmin[k];
            v = fminf(v, __shfl_xor_sync(0xffffffffu, v, 4));
            v = fminf(v, __shfl_xor_sync(0xffffffffu, v, 8));
            v = fminf(v, __shfl_xor_sync(0xffffffffu, v, 16));
            if (lane < 4)
                colpart[wr][64*wc + 32*h + 8*(k >> 1) + 2*lane + (k & 1)] = v;
        }
    }

    // reduce row-mins across lane&3: xor 1, 2
#pragma unroll
    for (int k = 0; k < 4; k++) {
        float v = rmin[k];
        v = fminf(v, __shfl_xor_sync(0xffffffffu, v, 1));
        v = fminf(v, __shfl_xor_sync(0xffffffffu, v, 2));
        if ((lane & 3) == 0)
            rowpart[wc][32*wr + 16*(k >> 1) + 8*(k & 1) + (lane >> 2)] = v;
    }
    __syncthreads();

    if (tid < 128) {
        float rv = fminf(rowpart[0][tid], rowpart[1][tid]);
        atomicMin(&g_rowmin[i0 + tid], __float_as_int(fmaxf(rv, 0.0f)));
        float cv = fminf(fminf(colpart[0][tid], colpart[1][tid]),
                         fminf(colpart[2][tid], colpart[3][tid]));
        atomicMin(&g_colmin[j0 + tid], __float_as_int(fmaxf(cv, 0.0f)));
    }
}

// ---------------------------------------------------------------- finalize
__global__ void finalize_kernel(int N, int M) {
    __shared__ float red[256];
    int  b     = blockIdx.x;
    bool isRow = (b < 64);
    int  idx   = (isRow ? b : b - 64) * 256 + threadIdx.x;
    float val  = 0.0f;
    int   lim  = isRow ? N : M;
    if (idx < lim) {
        float m   = fmaxf(__int_as_float(isRow ? g_rowmin[idx] : g_colmin[idx]),
                          0.0f);
        float inv = isRow ? g_invx[idx] : g_invy[idx];
        float u   = fmaf(2.0f * m, inv, 1.0f);
        val       = logf(u + sqrtf(fmaxf(u * u - 1.0f, 0.0f)));
    }
    red[threadIdx.x] = val;
    __syncthreads();
    for (int s = 128; s > 0; s >>= 1) {
        if (threadIdx.x < s) red[threadIdx.x] += red[threadIdx.x + s];
        __syncthreads();
    }
    if (threadIdx.x == 0)
        g_part[b] = red[0] * (isRow ? 1.0f / (float)N : 1.0f / (float)M);
}

__global__ void final_sum(float* out) {
    __shared__ float red[128];
    red[threadIdx.x] = g_part[threadIdx.x];
    __syncthreads();
    for (int s = 64; s > 0; s >>= 1) {
        if (threadIdx.x < s) red[threadIdx.x] += red[threadIdx.x + s];
        __syncthreads();
    }
    if (threadIdx.x == 0) out[0] = red[0];
}

// ---------------------------------------------------------------- launch
extern "C" void kernel_launch(void* const* d_in, const int* in_sizes, int n_in,
                              void* d_out, int out_size) {
    const float* X = (const float*)d_in[0];
    const float* Y = (const float*)d_in[1];
    int N = in_sizes[0] / 16;
    int M = in_sizes[1] / 16;

    int mx = (N > M ? N : M);
    prep_kernel<<<(mx + 255) / 256, 256>>>(X, Y, N, M);

    dim3 grid(M / 128, N / 128);
    pair_mma_kernel<<<grid, 256>>>();

    finalize_kernel<<<128, 256>>>(N, M);
    final_sum<<<1, 128>>>((float*)d_out);
}